// round 12
// baseline (speedup 1.0000x reference)
#include <cuda_runtime.h>

#define NN 8192
#define KD 512
#define FF 64
#define LRALPHA 0.2f
#define NB 8192
#define RMIN (-16.0f)
#define BSCALE 256.0f    /* NB / 32 range width */
#define CHUNK 64
#define NCHUNK 128       /* NN / CHUNK */
#define QSTRIDE 132
#define GEMMB 128        /* gemm blocks in kmain */
#define PREPB 512        /* prep blocks in kmain */

// ---------------- scratch (no allocations allowed; zero-initialized at load) ----------------
__device__ float g_h1[NN * FF];
__device__ float g_s1[NN];
__device__ float g_s2[NN];
__device__ float g_v2[KD];
__device__ int   g_cnt[NB];          // zeroed by kscat at end of every call
__device__ int   g_start[NB + 1];
__device__ int   g_cursor[NB];
__device__ int   g_bidx[NN];
__device__ int   g_sidx[NN];
__device__ float g_skey[NN];
__device__ float g_Q[(size_t)NN * QSTRIDE];
__device__ float g_totPos[NCHUNK * 66];
__device__ float g_totNeg[NCHUNK * 66];
__device__ float g_offPos[(NCHUNK + 1) * 66];
__device__ float g_offNeg[(NCHUNK + 1) * 66];
__device__ unsigned int g_v2flag;    // monotonic: stale-true readers see identical v2 bits
__device__ unsigned int g_scanflag;  // reset by kmain each call (stream-ordered)
__device__ unsigned int g_done;      // reset by kmain each call

// ---------------- 1. kmain: blocks 0..127 = GEMM h1 = x@W^T (+s1); 128..639 = prep s2/hist --
__global__ void __launch_bounds__(256) kmain(const float* __restrict__ X,
                                             const float* __restrict__ W,
                                             const float* __restrict__ w1,
                                             const float* __restrict__ w2,
                                             const float* __restrict__ Nmat) {
    const int t = threadIdx.x;
    const int bid = blockIdx.x;

    if (bid < GEMMB) {
        // ================= GEMM branch =================
        __shared__ float xs[2][32 * 64];
        __shared__ float ws[2][32 * 64];
        const int row0 = bid * 64;

        const int rl = t >> 2;
        const int kq = (t & 3) * 8;
        const int cs = rl ^ ((t & 3) << 3);
        const float* xp = X + (size_t)(row0 + rl) * KD + kq;
        const float* wp = W + (size_t)rl * KD + kq;

        float4 xa, xb, wa, wb;
        xa = *(const float4*)(xp + 0);  xb = *(const float4*)(xp + 4);
        wa = *(const float4*)(wp + 0);  wb = *(const float4*)(wp + 4);
        {
            float xv[8] = {xa.x, xa.y, xa.z, xa.w, xb.x, xb.y, xb.z, xb.w};
            float wv[8] = {wa.x, wa.y, wa.z, wa.w, wb.x, wb.y, wb.z, wb.w};
#pragma unroll
            for (int i = 0; i < 8; ++i) {
                xs[0][(kq + i) * 64 + cs] = xv[i];
                ws[0][(kq + i) * 64 + cs] = wv[i];
            }
        }
        __syncthreads();

        const int tr = t >> 4, tc = t & 15;
        const int r0 = tr * 4, c0 = tc * 4;
        float acc[4][4];
#pragma unroll
        for (int a = 0; a < 4; ++a)
#pragma unroll
            for (int b = 0; b < 4; ++b) acc[a][b] = 0.f;

        for (int ch = 0; ch < 16; ++ch) {
            const int cur = ch & 1;
            if (ch < 15) {
                const int ko = (ch + 1) * 32;
                xa = *(const float4*)(xp + ko);     xb = *(const float4*)(xp + ko + 4);
                wa = *(const float4*)(wp + ko);     wb = *(const float4*)(wp + ko + 4);
            }
#pragma unroll
            for (int kk = 0; kk < 32; ++kk) {
                const int swk = ((kk >> 3) & 3) << 3;
                float4 xv = *(const float4*)&xs[cur][kk * 64 + (r0 ^ swk)];
                float4 wv = *(const float4*)&ws[cur][kk * 64 + (c0 ^ swk)];
                acc[0][0] += xv.x * wv.x; acc[0][1] += xv.x * wv.y; acc[0][2] += xv.x * wv.z; acc[0][3] += xv.x * wv.w;
                acc[1][0] += xv.y * wv.x; acc[1][1] += xv.y * wv.y; acc[1][2] += xv.y * wv.z; acc[1][3] += xv.y * wv.w;
                acc[2][0] += xv.z * wv.x; acc[2][1] += xv.z * wv.y; acc[2][2] += xv.z * wv.z; acc[2][3] += xv.z * wv.w;
                acc[3][0] += xv.w * wv.x; acc[3][1] += xv.w * wv.y; acc[3][2] += xv.w * wv.z; acc[3][3] += xv.w * wv.w;
            }
            if (ch < 15) {
                const int nb = (ch + 1) & 1;
                float xv[8] = {xa.x, xa.y, xa.z, xa.w, xb.x, xb.y, xb.z, xb.w};
                float wv[8] = {wa.x, wa.y, wa.z, wa.w, wb.x, wb.y, wb.z, wb.w};
#pragma unroll
                for (int i = 0; i < 8; ++i) {
                    xs[nb][(kq + i) * 64 + cs] = xv[i];
                    ws[nb][(kq + i) * 64 + cs] = wv[i];
                }
                __syncthreads();
            }
        }

        float w1v[4];
#pragma unroll
        for (int ci = 0; ci < 4; ++ci) w1v[ci] = w1[c0 + ci];
#pragma unroll
        for (int ri = 0; ri < 4; ++ri) {
            const int row = row0 + r0 + ri;
            *(float4*)&g_h1[(size_t)row * FF + c0] =
                make_float4(acc[ri][0], acc[ri][1], acc[ri][2], acc[ri][3]);
            float p = acc[ri][0] * w1v[0] + acc[ri][1] * w1v[1] +
                      acc[ri][2] * w1v[2] + acc[ri][3] * w1v[3];
            p += __shfl_down_sync(0xffffffffu, p, 8, 16);
            p += __shfl_down_sync(0xffffffffu, p, 4, 16);
            p += __shfl_down_sync(0xffffffffu, p, 2, 16);
            p += __shfl_down_sync(0xffffffffu, p, 1, 16);
            if (tc == 0) g_s1[row] = p;
        }
    } else {
        // ================= prep branch =================
        __shared__ float v2s[KD];
        __shared__ float w2s[FF];
        const int pb = bid - GEMMB;     // 0..511

        if (pb == 1 && t == 0) { g_scanflag = 0u; g_done = 0u; }

        // prefetch this thread's N data (DRAM proceeds while we wait on v2)
        const int w = t >> 5, lane = t & 31;
        const int row = pb * 16 + w * 2;
        const float* p0 = Nmat + (size_t)row * KD;
        const float* p1 = p0 + KD;
        float4 u0, u1, u2, u3, q0, q1, q2, q3;
        u0 = *(const float4*)(p0 + 0 * 128 + lane * 4);
        u1 = *(const float4*)(p0 + 1 * 128 + lane * 4);
        u2 = *(const float4*)(p0 + 2 * 128 + lane * 4);
        u3 = *(const float4*)(p0 + 3 * 128 + lane * 4);
        q0 = *(const float4*)(p1 + 0 * 128 + lane * 4);
        q1 = *(const float4*)(p1 + 1 * 128 + lane * 4);
        q2 = *(const float4*)(p1 + 2 * 128 + lane * 4);
        q3 = *(const float4*)(p1 + 3 * 128 + lane * 4);

        if (pb == 0) {
            if (t < FF) w2s[t] = w2[t];
            __syncthreads();
            float a0 = 0.f, a1 = 0.f;
#pragma unroll
            for (int c = 0; c < FF; ++c) {
                a0 += W[c * KD + t] * w2s[c];
                a1 += W[c * KD + t + 256] * w2s[c];
            }
            g_v2[t] = a0; g_v2[t + 256] = a1;
            v2s[t] = a0; v2s[t + 256] = a1;
            __threadfence();
            __syncthreads();
            if (t == 0) atomicExch(&g_v2flag, 1u);
        } else {
            if (t == 0) {
                while (((volatile unsigned int*)&g_v2flag)[0] == 0u) __nanosleep(64);
            }
            __syncthreads();
            __threadfence();
            v2s[t] = g_v2[t];
            v2s[t + 256] = g_v2[t + 256];
            __syncthreads();
        }

        float a0 = 0.f, a1 = 0.f;
        const int k0 = lane * 4;
        a0 += u0.x * v2s[k0] + u0.y * v2s[k0 + 1] + u0.z * v2s[k0 + 2] + u0.w * v2s[k0 + 3];
        a1 += q0.x * v2s[k0] + q0.y * v2s[k0 + 1] + q0.z * v2s[k0 + 2] + q0.w * v2s[k0 + 3];
        a0 += u1.x * v2s[k0 + 128] + u1.y * v2s[k0 + 129] + u1.z * v2s[k0 + 130] + u1.w * v2s[k0 + 131];
        a1 += q1.x * v2s[k0 + 128] + q1.y * v2s[k0 + 129] + q1.z * v2s[k0 + 130] + q1.w * v2s[k0 + 131];
        a0 += u2.x * v2s[k0 + 256] + u2.y * v2s[k0 + 257] + u2.z * v2s[k0 + 258] + u2.w * v2s[k0 + 259];
        a1 += q2.x * v2s[k0 + 256] + q2.y * v2s[k0 + 257] + q2.z * v2s[k0 + 258] + q2.w * v2s[k0 + 259];
        a0 += u3.x * v2s[k0 + 384] + u3.y * v2s[k0 + 385] + u3.z * v2s[k0 + 386] + u3.w * v2s[k0 + 387];
        a1 += q3.x * v2s[k0 + 384] + q3.y * v2s[k0 + 385] + q3.z * v2s[k0 + 386] + q3.w * v2s[k0 + 387];
#pragma unroll
        for (int off = 16; off > 0; off >>= 1) {
            a0 += __shfl_xor_sync(0xffffffffu, a0, off);
            a1 += __shfl_xor_sync(0xffffffffu, a1, off);
        }
        if (lane == 0) {
            g_s2[row] = a0;
            g_s2[row + 1] = a1;
            const int b0 = min(max((int)((a0 - RMIN) * BSCALE), 0), NB - 1);
            const int b1 = min(max((int)((a1 - RMIN) * BSCALE), 0), NB - 1);
            g_bidx[row] = b0;
            g_bidx[row + 1] = b1;
            atomicAdd(&g_cnt[b0], 1);
            atomicAdd(&g_cnt[b1], 1);
        }
    }
}

// ---------------- 2. kscat: block-0 scan (others overlap-spin) -> scatter -> clear cnt ----
__global__ void __launch_bounds__(256) kscat() {
    __shared__ int wsum[8];
    const int t = threadIdx.x;
    const int bid = blockIdx.x;
    const int w = t >> 5, lane = t & 31;

    if (bid == 0) {
        int v[32];
#pragma unroll
        for (int q = 0; q < 8; ++q) {
            int4 c4 = ((const int4*)g_cnt)[t * 8 + q];
            v[q * 4 + 0] = c4.x; v[q * 4 + 1] = c4.y;
            v[q * 4 + 2] = c4.z; v[q * 4 + 3] = c4.w;
        }
        int tot = 0;
#pragma unroll
        for (int i = 0; i < 32; ++i) tot += v[i];
        int inc = tot;
#pragma unroll
        for (int off = 1; off < 32; off <<= 1) {
            int u = __shfl_up_sync(0xffffffffu, inc, off);
            if (lane >= off) inc += u;
        }
        if (lane == 31) wsum[w] = inc;
        __syncthreads();
        if (w == 0 && lane < 8) {
            int u = wsum[lane];
#pragma unroll
            for (int off = 1; off < 8; off <<= 1) {
                int x = __shfl_up_sync(0x000000ffu, u, off);
                if (lane >= off) u += x;
            }
            wsum[lane] = u;
        }
        __syncthreads();
        int run = inc - tot + (w > 0 ? wsum[w - 1] : 0);
#pragma unroll
        for (int q = 0; q < 8; ++q) {
            int4 s4;
            s4.x = run; run += v[q * 4 + 0];
            s4.y = run; run += v[q * 4 + 1];
            s4.z = run; run += v[q * 4 + 2];
            s4.w = run; run += v[q * 4 + 3];
            ((int4*)g_start)[t * 8 + q] = s4;
            ((int4*)g_cursor)[t * 8 + q] = s4;
        }
        if (t == 0) g_start[NB] = NN;
        __threadfence();
        __syncthreads();
        if (t == 0) atomicExch(&g_scanflag, 1u);
    } else {
        if (t == 0) {
            while (((volatile unsigned int*)&g_scanflag)[0] == 0u) __nanosleep(64);
        }
        __syncthreads();
        __threadfence();
    }

    // scatter: 32 blocks x 256 = 8192 items, 1 each (intra-bucket order is irrelevant)
    {
        const int j = bid * 256 + t;
        const int b = g_bidx[j];
        const int pos = atomicAdd(&g_cursor[b], 1);
        g_sidx[pos] = j;
        g_skey[pos] = g_s2[j];
    }
    // clear counts for next call (safe: scan already consumed them)
    g_cnt[bid * 256 + t] = 0;
}

// ---------------- 3. kphase1: chunk scans (warp-shuffle columns) + last-block offsets ------
__global__ void __launch_bounds__(1024) kphase1() {
    __shared__ float SH[2 * CHUNK * 66];
    __shared__ float GT[8 * 66];
    __shared__ float kky[CHUNK];
    __shared__ int   jj[CHUNK];
    __shared__ unsigned int rank_s;
    float* const SA = SH;
    const int tid = threadIdx.x;
    const int g = blockIdx.x;
    const int base = g * CHUNK;
    const int w = tid >> 5, lane = tid & 31;

    if (tid < CHUNK) {
        kky[tid] = g_skey[base + tid];
        jj[tid] = g_sidx[base + tid];
    }
    __syncthreads();

    for (int pass = 0; pass < 2; ++pass) {
#pragma unroll
        for (int th = 0; th < 2; ++th) {
            const int t = w + th * 32;
            const int j = jj[t];
            const float wv = (pass == 0) ? __expf(kky[t]) : __expf(LRALPHA * kky[t]);
            const float h0 = g_h1[(size_t)j * FF + lane];
            const float h1v = g_h1[(size_t)j * FF + 32 + lane];
            const int r = (pass == 0) ? (CHUNK - 1 - t) : t;
            SA[r * 66 + lane] = wv * h0;
            SA[r * 66 + 32 + lane] = wv * h1v;
            if (lane == 0) { SA[r * 66 + 64] = wv; SA[r * 66 + 65] = 0.f; }
        }
        __syncthreads();

        for (int c = w; c < 66; c += 32) {
            float v0 = SA[lane * 66 + c];
            float v1 = SA[(lane + 32) * 66 + c];
#pragma unroll
            for (int off = 1; off < 32; off <<= 1) {
                float u = __shfl_up_sync(0xffffffffu, v0, off);
                if (lane >= off) v0 += u;
            }
#pragma unroll
            for (int off = 1; off < 32; off <<= 1) {
                float u = __shfl_up_sync(0xffffffffu, v1, off);
                if (lane >= off) v1 += u;
            }
            v1 += __shfl_sync(0xffffffffu, v0, 31);
            SA[lane * 66 + c] = v0;
            SA[(lane + 32) * 66 + c] = v1;
        }
        __syncthreads();

        if (pass == 0) {
            for (int e = tid; e < CHUNK * 66; e += 1024) {
                const int t = e / 66, c = e - t * 66;
                g_Q[(size_t)(base + t) * QSTRIDE + c] = SA[(CHUNK - 1 - t) * 66 + c];
            }
            if (tid < 65) g_totPos[g * 66 + tid] = SA[(CHUNK - 1) * 66 + tid];
        } else {
            for (int e = tid; e < CHUNK * 66; e += 1024) {
                const int t = e / 66, c = e - t * 66;
                g_Q[(size_t)(base + t) * QSTRIDE + 66 + c] =
                    (t > 0) ? SA[(t - 1) * 66 + c] : 0.f;
            }
            if (tid < 65) g_totNeg[g * 66 + tid] = SA[(CHUNK - 1) * 66 + tid];
        }
        __syncthreads();
    }

    if (tid == 0) { __threadfence(); rank_s = atomicAdd(&g_done, 1u); }
    __syncthreads();
    if (rank_s != NCHUNK - 1) return;
    __threadfence();

    const int grp = tid / 66, c = tid % 66;

    for (int e = tid; e < NCHUNK * 66; e += 1024) SH[e] = g_totPos[e];
    __syncthreads();
    if (tid < 528) {
        float acc = 0.f;
        for (int i = 15; i >= 0; --i) {
            const int gg = grp * 16 + i;
            const float v = SH[gg * 66 + c];
            SH[gg * 66 + c] = acc;
            acc += v;
        }
        GT[grp * 66 + c] = acc;
    }
    __syncthreads();
    if (tid < 66) {
        float acc = 0.f;
        for (int gg = 7; gg >= 0; --gg) {
            const float v = GT[gg * 66 + tid];
            GT[gg * 66 + tid] = acc;
            acc += v;
        }
        g_offPos[NCHUNK * 66 + tid] = 0.f;
    }
    __syncthreads();
    if (tid < 528) {
        const float o = GT[grp * 66 + c];
        for (int i = 0; i < 16; ++i) {
            const int gg = grp * 16 + i;
            g_offPos[gg * 66 + c] = SH[gg * 66 + c] + o;
        }
    }
    __syncthreads();

    for (int e = tid; e < NCHUNK * 66; e += 1024) SH[e] = g_totNeg[e];
    __syncthreads();
    if (tid < 528) {
        float acc = 0.f;
        for (int i = 0; i < 16; ++i) {
            const int gg = grp * 16 + i;
            const float v = SH[gg * 66 + c];
            SH[gg * 66 + c] = acc;
            acc += v;
        }
        GT[grp * 66 + c] = acc;
    }
    __syncthreads();
    if (tid < 66) {
        float acc = 0.f;
        for (int gg = 0; gg < 8; ++gg) {
            const float v = GT[gg * 66 + tid];
            GT[gg * 66 + tid] = acc;
            acc += v;
        }
        g_offNeg[NCHUNK * 66 + tid] = acc;
    }
    __syncthreads();
    if (tid < 528) {
        const float o = GT[grp * 66 + c];
        for (int i = 0; i < 16; ++i) {
            const int gg = grp * 16 + i;
            g_offNeg[gg * 66 + c] = SH[gg * 66 + c] + o;
        }
    }
}

// ---------------- 4. kquery: bucket lookup + straddle items + combine ----------------
__global__ void kquery(float* __restrict__ out) {
    const int t = threadIdx.x;
    const int w = t >> 5, lane = t & 31;
    const int i = blockIdx.x * 8 + w;

    const float s1v = g_s1[i];
    const float tau = -s1v;
    const float e1 = __expf(s1v);
    const float e1a = __expf(LRALPHA * s1v);

    // bucket of tau (same monotone fp binning as keys -> boundary-consistent)
    const int bt = min(max((int)((tau - RMIN) * BSCALE), 0), NB - 1);
    const int r0 = g_start[bt];
    const int r1 = g_start[bt + 1];

    // pos suffix from rank r1 (all ranks >= r1 have key >= tau)
    float qA0 = 0.f, qA1 = 0.f, qAs = 0.f;
    if (r1 < NN) {
        const float* q = g_Q + (size_t)r1 * QSTRIDE;
        qA0 = q[lane]; qA1 = q[lane + 32]; qAs = q[64];
    }
    const float* op = g_offPos + (r1 >> 6) * 66;
    float A0 = qA0 + op[lane], A1 = qA1 + op[lane + 32], As = qAs + op[64];

    // neg prefix over ranks < r0 (all have key < tau)
    float qB0 = 0.f, qB1 = 0.f, qBs = 0.f;
    if (r0 < NN) {
        const float* q = g_Q + (size_t)r0 * QSTRIDE;
        qB0 = q[66 + lane]; qB1 = q[66 + lane + 32]; qBs = q[66 + 64];
    }
    const float* on = g_offNeg + (r0 >> 6) * 66;
    float B0 = qB0 + on[lane], B1 = qB1 + on[lane + 32], Bs = qBs + on[64];

    // exact pass over the straddling bucket [r0, r1)
    for (int k = r0; k < r1; ++k) {
        const float key = g_skey[k];
        const int j = g_sidx[k];
        const float h0 = g_h1[(size_t)j * FF + lane];
        const float hv = g_h1[(size_t)j * FF + 32 + lane];
        if (key >= tau) {
            const float e = __expf(key);
            A0 += e * h0; A1 += e * hv; As += e;
        } else {
            const float e = __expf(LRALPHA * key);
            B0 += e * h0; B1 += e * hv; Bs += e;
        }
    }

    const float den = e1 * As + e1a * Bs;
    const float inv = 1.0f / den;
    out[(size_t)i * FF + lane]      = (e1 * A0 + e1a * B0) * inv;
    out[(size_t)i * FF + 32 + lane] = (e1 * A1 + e1a * B1) * inv;
}

// ---------------- launch ----------------
extern "C" void kernel_launch(void* const* d_in, const int* in_sizes, int n_in,
                              void* d_out, int out_size) {
    const float* x  = (const float*)d_in[0];
    const float* nm = (const float*)d_in[1];
    const float* W  = (const float*)d_in[2];
    const float* w1 = (const float*)d_in[3];
    const float* w2 = (const float*)d_in[4];
    float* out = (float*)d_out;

    kmain<<<GEMMB + PREPB, 256>>>(x, W, w1, w2, nm);
    kscat<<<32, 256>>>();
    kphase1<<<NCHUNK, 1024>>>();
    kquery<<<NN / 8, 256>>>(out);
}

// round 13
// speedup vs baseline: 1.0317x; 1.0317x over previous
#include <cuda_runtime.h>

#define NN 8192
#define KD 512
#define FF 64
#define LRALPHA 0.2f
#define NB 8192
#define RMIN (-16.0f)
#define BSCALE 256.0f    /* NB / 32 range width */
#define CHUNK 64
#define NCHUNK 128       /* NN / CHUNK */
#define QSTRIDE 132
#define GEMMB 128        /* gemm blocks in kmain */
#define PREPB 512        /* prep blocks in kmain */

// ---------------- scratch (no allocations allowed; zero-initialized at load) ----------------
__device__ float g_h1[NN * FF];
__device__ float g_s1[NN];
__device__ float g_s2[NN];
__device__ float g_v2[KD];
__device__ int   g_cnt[NB];          // zeroed by kscat at end of every call
__device__ int   g_start[NB + 1];
__device__ int   g_cursor[NB];
__device__ int   g_bidx[NN];
__device__ int   g_sidx[NN];
__device__ float g_skey[NN];
__device__ float g_Q[(size_t)NN * QSTRIDE];
__device__ float g_totPos[NCHUNK * 66];
__device__ float g_totNeg[NCHUNK * 66];
__device__ float g_offPos[(NCHUNK + 1) * 66];
__device__ float g_offNeg[(NCHUNK + 1) * 66];
__device__ unsigned int g_v2flag;    // monotonic: stale-true readers see identical v2 bits
__device__ unsigned int g_scanflag;  // reset by kmain each call (stream-ordered)
__device__ unsigned int g_done;      // reset by kmain each call

// ---------------- 1. kmain: blocks 0..127 = GEMM h1 = x@W^T (+s1); 128..639 = prep s2/hist --
__global__ void __launch_bounds__(256) kmain(const float* __restrict__ X,
                                             const float* __restrict__ W,
                                             const float* __restrict__ w1,
                                             const float* __restrict__ w2,
                                             const float* __restrict__ Nmat) {
    const int t = threadIdx.x;
    const int bid = blockIdx.x;

    if (bid < GEMMB) {
        // ================= GEMM branch =================
        __shared__ float xs[2][32 * 64];
        __shared__ float ws[2][32 * 64];
        const int row0 = bid * 64;

        const int rl = t >> 2;
        const int kq = (t & 3) * 8;
        const int cs = rl ^ ((t & 3) << 3);
        const float* xp = X + (size_t)(row0 + rl) * KD + kq;
        const float* wp = W + (size_t)rl * KD + kq;

        float4 xa, xb, wa, wb;
        xa = *(const float4*)(xp + 0);  xb = *(const float4*)(xp + 4);
        wa = *(const float4*)(wp + 0);  wb = *(const float4*)(wp + 4);
        {
            float xv[8] = {xa.x, xa.y, xa.z, xa.w, xb.x, xb.y, xb.z, xb.w};
            float wv[8] = {wa.x, wa.y, wa.z, wa.w, wb.x, wb.y, wb.z, wb.w};
#pragma unroll
            for (int i = 0; i < 8; ++i) {
                xs[0][(kq + i) * 64 + cs] = xv[i];
                ws[0][(kq + i) * 64 + cs] = wv[i];
            }
        }
        __syncthreads();

        const int tr = t >> 4, tc = t & 15;
        const int r0 = tr * 4, c0 = tc * 4;
        float acc[4][4];
#pragma unroll
        for (int a = 0; a < 4; ++a)
#pragma unroll
            for (int b = 0; b < 4; ++b) acc[a][b] = 0.f;

        for (int ch = 0; ch < 16; ++ch) {
            const int cur = ch & 1;
            if (ch < 15) {
                const int ko = (ch + 1) * 32;
                xa = *(const float4*)(xp + ko);     xb = *(const float4*)(xp + ko + 4);
                wa = *(const float4*)(wp + ko);     wb = *(const float4*)(wp + ko + 4);
            }
#pragma unroll
            for (int kk = 0; kk < 32; ++kk) {
                const int swk = ((kk >> 3) & 3) << 3;
                float4 xv = *(const float4*)&xs[cur][kk * 64 + (r0 ^ swk)];
                float4 wv = *(const float4*)&ws[cur][kk * 64 + (c0 ^ swk)];
                acc[0][0] += xv.x * wv.x; acc[0][1] += xv.x * wv.y; acc[0][2] += xv.x * wv.z; acc[0][3] += xv.x * wv.w;
                acc[1][0] += xv.y * wv.x; acc[1][1] += xv.y * wv.y; acc[1][2] += xv.y * wv.z; acc[1][3] += xv.y * wv.w;
                acc[2][0] += xv.z * wv.x; acc[2][1] += xv.z * wv.y; acc[2][2] += xv.z * wv.z; acc[2][3] += xv.z * wv.w;
                acc[3][0] += xv.w * wv.x; acc[3][1] += xv.w * wv.y; acc[3][2] += xv.w * wv.z; acc[3][3] += xv.w * wv.w;
            }
            if (ch < 15) {
                const int nb = (ch + 1) & 1;
                float xv[8] = {xa.x, xa.y, xa.z, xa.w, xb.x, xb.y, xb.z, xb.w};
                float wv[8] = {wa.x, wa.y, wa.z, wa.w, wb.x, wb.y, wb.z, wb.w};
#pragma unroll
                for (int i = 0; i < 8; ++i) {
                    xs[nb][(kq + i) * 64 + cs] = xv[i];
                    ws[nb][(kq + i) * 64 + cs] = wv[i];
                }
                __syncthreads();
            }
        }

        float w1v[4];
#pragma unroll
        for (int ci = 0; ci < 4; ++ci) w1v[ci] = w1[c0 + ci];
#pragma unroll
        for (int ri = 0; ri < 4; ++ri) {
            const int row = row0 + r0 + ri;
            *(float4*)&g_h1[(size_t)row * FF + c0] =
                make_float4(acc[ri][0], acc[ri][1], acc[ri][2], acc[ri][3]);
            float p = acc[ri][0] * w1v[0] + acc[ri][1] * w1v[1] +
                      acc[ri][2] * w1v[2] + acc[ri][3] * w1v[3];
            p += __shfl_down_sync(0xffffffffu, p, 8, 16);
            p += __shfl_down_sync(0xffffffffu, p, 4, 16);
            p += __shfl_down_sync(0xffffffffu, p, 2, 16);
            p += __shfl_down_sync(0xffffffffu, p, 1, 16);
            if (tc == 0) g_s1[row] = p;
        }
    } else {
        // ================= prep branch =================
        __shared__ float v2s[KD];
        __shared__ float w2s[FF];
        const int pb = bid - GEMMB;     // 0..511

        if (pb == 1 && t == 0) { g_scanflag = 0u; g_done = 0u; }

        // prefetch this thread's N data (DRAM proceeds while we wait on v2)
        const int w = t >> 5, lane = t & 31;
        const int row = pb * 16 + w * 2;
        const float* p0 = Nmat + (size_t)row * KD;
        const float* p1 = p0 + KD;
        float4 u0, u1, u2, u3, q0, q1, q2, q3;
        u0 = *(const float4*)(p0 + 0 * 128 + lane * 4);
        u1 = *(const float4*)(p0 + 1 * 128 + lane * 4);
        u2 = *(const float4*)(p0 + 2 * 128 + lane * 4);
        u3 = *(const float4*)(p0 + 3 * 128 + lane * 4);
        q0 = *(const float4*)(p1 + 0 * 128 + lane * 4);
        q1 = *(const float4*)(p1 + 1 * 128 + lane * 4);
        q2 = *(const float4*)(p1 + 2 * 128 + lane * 4);
        q3 = *(const float4*)(p1 + 3 * 128 + lane * 4);

        if (pb == 0) {
            if (t < FF) w2s[t] = w2[t];
            __syncthreads();
            float a0 = 0.f, a1 = 0.f;
#pragma unroll
            for (int c = 0; c < FF; ++c) {
                a0 += W[c * KD + t] * w2s[c];
                a1 += W[c * KD + t + 256] * w2s[c];
            }
            g_v2[t] = a0; g_v2[t + 256] = a1;
            v2s[t] = a0; v2s[t + 256] = a1;
            __threadfence();
            __syncthreads();
            if (t == 0) atomicExch(&g_v2flag, 1u);
        } else {
            if (t == 0) {
                while (((volatile unsigned int*)&g_v2flag)[0] == 0u) __nanosleep(64);
            }
            __syncthreads();
            __threadfence();
            v2s[t] = g_v2[t];
            v2s[t + 256] = g_v2[t + 256];
            __syncthreads();
        }

        float a0 = 0.f, a1 = 0.f;
        const int k0 = lane * 4;
        a0 += u0.x * v2s[k0] + u0.y * v2s[k0 + 1] + u0.z * v2s[k0 + 2] + u0.w * v2s[k0 + 3];
        a1 += q0.x * v2s[k0] + q0.y * v2s[k0 + 1] + q0.z * v2s[k0 + 2] + q0.w * v2s[k0 + 3];
        a0 += u1.x * v2s[k0 + 128] + u1.y * v2s[k0 + 129] + u1.z * v2s[k0 + 130] + u1.w * v2s[k0 + 131];
        a1 += q1.x * v2s[k0 + 128] + q1.y * v2s[k0 + 129] + q1.z * v2s[k0 + 130] + q1.w * v2s[k0 + 131];
        a0 += u2.x * v2s[k0 + 256] + u2.y * v2s[k0 + 257] + u2.z * v2s[k0 + 258] + u2.w * v2s[k0 + 259];
        a1 += q2.x * v2s[k0 + 256] + q2.y * v2s[k0 + 257] + q2.z * v2s[k0 + 258] + q2.w * v2s[k0 + 259];
        a0 += u3.x * v2s[k0 + 384] + u3.y * v2s[k0 + 385] + u3.z * v2s[k0 + 386] + u3.w * v2s[k0 + 387];
        a1 += q3.x * v2s[k0 + 384] + q3.y * v2s[k0 + 385] + q3.z * v2s[k0 + 386] + q3.w * v2s[k0 + 387];
#pragma unroll
        for (int off = 16; off > 0; off >>= 1) {
            a0 += __shfl_xor_sync(0xffffffffu, a0, off);
            a1 += __shfl_xor_sync(0xffffffffu, a1, off);
        }
        if (lane == 0) {
            g_s2[row] = a0;
            g_s2[row + 1] = a1;
            const int b0 = min(max((int)((a0 - RMIN) * BSCALE), 0), NB - 1);
            const int b1 = min(max((int)((a1 - RMIN) * BSCALE), 0), NB - 1);
            g_bidx[row] = b0;
            g_bidx[row + 1] = b1;
            atomicAdd(&g_cnt[b0], 1);
            atomicAdd(&g_cnt[b1], 1);
        }
    }
}

// ---------------- 2. kscat: block-0 scan (others overlap-spin) -> scatter -> clear cnt ----
__global__ void __launch_bounds__(256) kscat() {
    __shared__ int wsum[8];
    const int t = threadIdx.x;
    const int bid = blockIdx.x;
    const int w = t >> 5, lane = t & 31;

    if (bid == 0) {
        int v[32];
#pragma unroll
        for (int q = 0; q < 8; ++q) {
            int4 c4 = ((const int4*)g_cnt)[t * 8 + q];
            v[q * 4 + 0] = c4.x; v[q * 4 + 1] = c4.y;
            v[q * 4 + 2] = c4.z; v[q * 4 + 3] = c4.w;
        }
        int tot = 0;
#pragma unroll
        for (int i = 0; i < 32; ++i) tot += v[i];
        int inc = tot;
#pragma unroll
        for (int off = 1; off < 32; off <<= 1) {
            int u = __shfl_up_sync(0xffffffffu, inc, off);
            if (lane >= off) inc += u;
        }
        if (lane == 31) wsum[w] = inc;
        __syncthreads();
        if (w == 0 && lane < 8) {
            int u = wsum[lane];
#pragma unroll
            for (int off = 1; off < 8; off <<= 1) {
                int x = __shfl_up_sync(0x000000ffu, u, off);
                if (lane >= off) u += x;
            }
            wsum[lane] = u;
        }
        __syncthreads();
        int run = inc - tot + (w > 0 ? wsum[w - 1] : 0);
#pragma unroll
        for (int q = 0; q < 8; ++q) {
            int4 s4;
            s4.x = run; run += v[q * 4 + 0];
            s4.y = run; run += v[q * 4 + 1];
            s4.z = run; run += v[q * 4 + 2];
            s4.w = run; run += v[q * 4 + 3];
            ((int4*)g_start)[t * 8 + q] = s4;
            ((int4*)g_cursor)[t * 8 + q] = s4;
        }
        if (t == 0) g_start[NB] = NN;
        __threadfence();
        __syncthreads();
        if (t == 0) atomicExch(&g_scanflag, 1u);
    } else {
        if (t == 0) {
            while (((volatile unsigned int*)&g_scanflag)[0] == 0u) __nanosleep(64);
        }
        __syncthreads();
        __threadfence();
    }

    // scatter: 32 blocks x 256 = 8192 items, 1 each
    {
        const int j = bid * 256 + t;
        const int b = g_bidx[j];
        const int pos = atomicAdd(&g_cursor[b], 1);
        g_sidx[pos] = j;
        g_skey[pos] = g_s2[j];
    }
    // clear counts for next call (safe: scan already consumed them)
    g_cnt[bid * 256 + t] = 0;
}

// ---------------- 3. kbsort: warp bitonic per bucket (deterministic) ----------------
__global__ void __launch_bounds__(256) kbsort() {
    const int wrp = threadIdx.x >> 5, lane = threadIdx.x & 31;
    const int b = blockIdx.x * 8 + wrp;
    const int s = g_start[b];
    const int m = g_start[b + 1] - s;
    if (m <= 1) return;
    if (m <= 32) {
        float key; int idx;
        if (lane < m) { key = g_skey[s + lane]; idx = g_sidx[s + lane]; }
        else { key = __int_as_float(0x7f800000); idx = 0x7f000000 + lane; }
#pragma unroll
        for (int k = 2; k <= 32; k <<= 1) {
#pragma unroll
            for (int j = k >> 1; j >= 1; j >>= 1) {
                float ok = __shfl_xor_sync(0xffffffffu, key, j);
                int   oi = __shfl_xor_sync(0xffffffffu, idx, j);
                const bool up = ((lane & k) == 0);
                const bool lower = ((lane & j) == 0);
                const bool oless = (ok < key) || (ok == key && oi < idx);
                const bool take = (lower == up) ? oless : !oless;
                if (take) { key = ok; idx = oi; }
            }
        }
        if (lane < m) { g_skey[s + lane] = key; g_sidx[s + lane] = idx; }
    } else if (lane == 0) {
        for (int a = s + 1; a < s + m; ++a) {
            const float k = g_skey[a];
            const int id = g_sidx[a];
            int p = a - 1;
            while (p >= s) {
                const float kp = g_skey[p];
                const int ip = g_sidx[p];
                if (kp > k || (kp == k && ip > id)) {
                    g_skey[p + 1] = kp; g_sidx[p + 1] = ip; --p;
                } else break;
            }
            g_skey[p + 1] = k; g_sidx[p + 1] = id;
        }
    }
}

// ---------------- 4. kphase1: chunk scans (warp-shuffle columns) + last-block offsets ------
__global__ void __launch_bounds__(1024) kphase1() {
    __shared__ float SH[2 * CHUNK * 66];
    __shared__ float GT[8 * 66];
    __shared__ float kky[CHUNK];
    __shared__ int   jj[CHUNK];
    __shared__ unsigned int rank_s;
    float* const SA = SH;
    const int tid = threadIdx.x;
    const int g = blockIdx.x;
    const int base = g * CHUNK;
    const int w = tid >> 5, lane = tid & 31;

    if (tid < CHUNK) {
        kky[tid] = g_skey[base + tid];
        jj[tid] = g_sidx[base + tid];
    }
    __syncthreads();

    for (int pass = 0; pass < 2; ++pass) {
#pragma unroll
        for (int th = 0; th < 2; ++th) {
            const int t = w + th * 32;
            const int j = jj[t];
            const float wv = (pass == 0) ? __expf(kky[t]) : __expf(LRALPHA * kky[t]);
            const float h0 = g_h1[(size_t)j * FF + lane];
            const float h1v = g_h1[(size_t)j * FF + 32 + lane];
            const int r = (pass == 0) ? (CHUNK - 1 - t) : t;
            SA[r * 66 + lane] = wv * h0;
            SA[r * 66 + 32 + lane] = wv * h1v;
            if (lane == 0) { SA[r * 66 + 64] = wv; SA[r * 66 + 65] = 0.f; }
        }
        __syncthreads();

        for (int c = w; c < 66; c += 32) {
            float v0 = SA[lane * 66 + c];
            float v1 = SA[(lane + 32) * 66 + c];
#pragma unroll
            for (int off = 1; off < 32; off <<= 1) {
                float u = __shfl_up_sync(0xffffffffu, v0, off);
                if (lane >= off) v0 += u;
            }
#pragma unroll
            for (int off = 1; off < 32; off <<= 1) {
                float u = __shfl_up_sync(0xffffffffu, v1, off);
                if (lane >= off) v1 += u;
            }
            v1 += __shfl_sync(0xffffffffu, v0, 31);
            SA[lane * 66 + c] = v0;
            SA[(lane + 32) * 66 + c] = v1;
        }
        __syncthreads();

        if (pass == 0) {
            for (int e = tid; e < CHUNK * 66; e += 1024) {
                const int t = e / 66, c = e - t * 66;
                g_Q[(size_t)(base + t) * QSTRIDE + c] = SA[(CHUNK - 1 - t) * 66 + c];
            }
            if (tid < 65) g_totPos[g * 66 + tid] = SA[(CHUNK - 1) * 66 + tid];
        } else {
            for (int e = tid; e < CHUNK * 66; e += 1024) {
                const int t = e / 66, c = e - t * 66;
                g_Q[(size_t)(base + t) * QSTRIDE + 66 + c] =
                    (t > 0) ? SA[(t - 1) * 66 + c] : 0.f;
            }
            if (tid < 65) g_totNeg[g * 66 + tid] = SA[(CHUNK - 1) * 66 + tid];
        }
        __syncthreads();
    }

    if (tid == 0) { __threadfence(); rank_s = atomicAdd(&g_done, 1u); }
    __syncthreads();
    if (rank_s != NCHUNK - 1) return;
    __threadfence();

    const int grp = tid / 66, c = tid % 66;

    for (int e = tid; e < NCHUNK * 66; e += 1024) SH[e] = g_totPos[e];
    __syncthreads();
    if (tid < 528) {
        float acc = 0.f;
        for (int i = 15; i >= 0; --i) {
            const int gg = grp * 16 + i;
            const float v = SH[gg * 66 + c];
            SH[gg * 66 + c] = acc;
            acc += v;
        }
        GT[grp * 66 + c] = acc;
    }
    __syncthreads();
    if (tid < 66) {
        float acc = 0.f;
        for (int gg = 7; gg >= 0; --gg) {
            const float v = GT[gg * 66 + tid];
            GT[gg * 66 + tid] = acc;
            acc += v;
        }
        g_offPos[NCHUNK * 66 + tid] = 0.f;
    }
    __syncthreads();
    if (tid < 528) {
        const float o = GT[grp * 66 + c];
        for (int i = 0; i < 16; ++i) {
            const int gg = grp * 16 + i;
            g_offPos[gg * 66 + c] = SH[gg * 66 + c] + o;
        }
    }
    __syncthreads();

    for (int e = tid; e < NCHUNK * 66; e += 1024) SH[e] = g_totNeg[e];
    __syncthreads();
    if (tid < 528) {
        float acc = 0.f;
        for (int i = 0; i < 16; ++i) {
            const int gg = grp * 16 + i;
            const float v = SH[gg * 66 + c];
            SH[gg * 66 + c] = acc;
            acc += v;
        }
        GT[grp * 66 + c] = acc;
    }
    __syncthreads();
    if (tid < 66) {
        float acc = 0.f;
        for (int gg = 0; gg < 8; ++gg) {
            const float v = GT[gg * 66 + tid];
            GT[gg * 66 + tid] = acc;
            acc += v;
        }
        g_offNeg[NCHUNK * 66 + tid] = acc;
    }
    __syncthreads();
    if (tid < 528) {
        const float o = GT[grp * 66 + c];
        for (int i = 0; i < 16; ++i) {
            const int gg = grp * 16 + i;
            g_offNeg[gg * 66 + c] = SH[gg * 66 + c] + o;
        }
    }
}

// ---------------- 5. kquery: bucket-narrowed binary search + combine ----------------
__global__ void kquery(float* __restrict__ out) {
    const int t = threadIdx.x;
    const int w = t >> 5, lane = t & 31;
    const int i = blockIdx.x * 8 + w;

    const float s1v = g_s1[i];
    const float tau = -s1v;
    const float e1 = __expf(s1v);
    const float e1a = __expf(LRALPHA * s1v);

    // narrow to tau's bucket: keys < tau only in buckets <= bt, keys >= tau only >= bt
    const int bt = min(max((int)((tau - RMIN) * BSCALE), 0), NB - 1);
    int lo = g_start[bt], hi = g_start[bt + 1];
    while (lo < hi) {
        const int mid = (lo + hi) >> 1;
        if (g_skey[mid] < tau) lo = mid + 1; else hi = mid;
    }
    const int r = lo;  // first rank with key >= tau

    float qA0 = 0.f, qA1 = 0.f, qAs = 0.f, qB0 = 0.f, qB1 = 0.f, qBs = 0.f;
    if (r < NN) {
        const float* q = g_Q + (size_t)r * QSTRIDE;
        qA0 = q[lane];       qA1 = q[lane + 32];       qAs = q[64];
        qB0 = q[66 + lane];  qB1 = q[66 + lane + 32];  qBs = q[66 + 64];
    }
    const int g = r >> 6;
    const float* op = g_offPos + g * 66;
    const float* on = g_offNeg + g * 66;
    const float A0 = qA0 + op[lane], A1 = qA1 + op[lane + 32], As = qAs + op[64];
    const float B0 = qB0 + on[lane], B1 = qB1 + on[lane + 32], Bs = qBs + on[64];

    const float den = e1 * As + e1a * Bs;
    const float inv = 1.0f / den;
    out[(size_t)i * FF + lane]      = (e1 * A0 + e1a * B0) * inv;
    out[(size_t)i * FF + 32 + lane] = (e1 * A1 + e1a * B1) * inv;
}

// ---------------- launch ----------------
extern "C" void kernel_launch(void* const* d_in, const int* in_sizes, int n_in,
                              void* d_out, int out_size) {
    const float* x  = (const float*)d_in[0];
    const float* nm = (const float*)d_in[1];
    const float* W  = (const float*)d_in[2];
    const float* w1 = (const float*)d_in[3];
    const float* w2 = (const float*)d_in[4];
    float* out = (float*)d_out;

    kmain<<<GEMMB + PREPB, 256>>>(x, W, w1, w2, nm);
    kscat<<<32, 256>>>();
    kbsort<<<NB / 8, 256>>>();
    kphase1<<<NCHUNK, 1024>>>();
    kquery<<<NN / 8, 256>>>(out);
}

// round 14
// speedup vs baseline: 1.2337x; 1.1958x over previous
#include <cuda_runtime.h>

#define NN 8192
#define KD 512
#define FF 64
#define LRALPHA 0.2f
#define NB 8192
#define RMIN (-16.0f)
#define BSCALE 256.0f    /* NB / 32 range width */
#define CHUNK 64
#define NCHUNK 128       /* NN / CHUNK */
#define QSTRIDE 132

// ---------------- scratch (no allocations allowed; zero-initialized at load) ----------------
__device__ float g_h1[NN * FF];
__device__ float g_s1[NN];
__device__ float g_s2[NN];
__device__ float g_v2[KD];
__device__ int   g_cnt[NB];          // zeroed by kscat at end of every call
__device__ int   g_start[NB + 1];
__device__ int   g_cursor[NB];
__device__ int   g_bidx[NN];
__device__ int   g_sidx[NN];
__device__ float g_skey[NN];
__device__ float g_Q[(size_t)NN * QSTRIDE];
__device__ float g_totPos[NCHUNK * 66];
__device__ float g_totNeg[NCHUNK * 66];
__device__ float g_offPos[(NCHUNK + 1) * 66];
__device__ float g_offNeg[(NCHUNK + 1) * 66];
__device__ unsigned int g_v2flag;    // monotonic: stale-true readers see identical v2 bits
__device__ unsigned int g_scanflag;  // reset by kprep each call (stream-ordered)
__device__ unsigned int g_done;      // reset by kprep each call

// ---------------- 1. kprep: v2 (block 0) + s2/bidx/hist (all blocks), prefetch-overlapped ----
__global__ void __launch_bounds__(256) kprep(const float* __restrict__ W,
                                             const float* __restrict__ w2,
                                             const float* __restrict__ Nmat) {
    __shared__ float v2s[KD];
    const int t = threadIdx.x;
    const int bid = blockIdx.x;

    if (bid == 1 && t == 0) { g_scanflag = 0u; g_done = 0u; }

    const int w = t >> 5, lane = t & 31;
    const int row = bid * 16 + w * 2;
    const float* p0 = Nmat + (size_t)row * KD;
    const float* p1 = p0 + KD;
    float4 u0, u1, u2, u3, q0, q1, q2, q3;
    u0 = *(const float4*)(p0 + 0 * 128 + lane * 4);
    u1 = *(const float4*)(p0 + 1 * 128 + lane * 4);
    u2 = *(const float4*)(p0 + 2 * 128 + lane * 4);
    u3 = *(const float4*)(p0 + 3 * 128 + lane * 4);
    q0 = *(const float4*)(p1 + 0 * 128 + lane * 4);
    q1 = *(const float4*)(p1 + 1 * 128 + lane * 4);
    q2 = *(const float4*)(p1 + 2 * 128 + lane * 4);
    q3 = *(const float4*)(p1 + 3 * 128 + lane * 4);

    if (bid == 0) {
        __shared__ float w2s[FF];
        if (t < FF) w2s[t] = w2[t];
        __syncthreads();
        float a0 = 0.f, a1 = 0.f;
#pragma unroll
        for (int c = 0; c < FF; ++c) {
            a0 += W[c * KD + t] * w2s[c];
            a1 += W[c * KD + t + 256] * w2s[c];
        }
        g_v2[t] = a0; g_v2[t + 256] = a1;
        v2s[t] = a0; v2s[t + 256] = a1;
        __threadfence();
        __syncthreads();
        if (t == 0) atomicExch(&g_v2flag, 1u);
    } else {
        if (t == 0) {
            while (((volatile unsigned int*)&g_v2flag)[0] == 0u) __nanosleep(64);
        }
        __syncthreads();
        __threadfence();
        v2s[t] = g_v2[t];
        v2s[t + 256] = g_v2[t + 256];
        __syncthreads();
    }

    float a0 = 0.f, a1 = 0.f;
    const int k0 = lane * 4;
    a0 += u0.x * v2s[k0] + u0.y * v2s[k0 + 1] + u0.z * v2s[k0 + 2] + u0.w * v2s[k0 + 3];
    a1 += q0.x * v2s[k0] + q0.y * v2s[k0 + 1] + q0.z * v2s[k0 + 2] + q0.w * v2s[k0 + 3];
    a0 += u1.x * v2s[k0 + 128] + u1.y * v2s[k0 + 129] + u1.z * v2s[k0 + 130] + u1.w * v2s[k0 + 131];
    a1 += q1.x * v2s[k0 + 128] + q1.y * v2s[k0 + 129] + q1.z * v2s[k0 + 130] + q1.w * v2s[k0 + 131];
    a0 += u2.x * v2s[k0 + 256] + u2.y * v2s[k0 + 257] + u2.z * v2s[k0 + 258] + u2.w * v2s[k0 + 259];
    a1 += q2.x * v2s[k0 + 256] + q2.y * v2s[k0 + 257] + q2.z * v2s[k0 + 258] + q2.w * v2s[k0 + 259];
    a0 += u3.x * v2s[k0 + 384] + u3.y * v2s[k0 + 385] + u3.z * v2s[k0 + 386] + u3.w * v2s[k0 + 387];
    a1 += q3.x * v2s[k0 + 384] + q3.y * v2s[k0 + 385] + q3.z * v2s[k0 + 386] + q3.w * v2s[k0 + 387];
#pragma unroll
    for (int off = 16; off > 0; off >>= 1) {
        a0 += __shfl_xor_sync(0xffffffffu, a0, off);
        a1 += __shfl_xor_sync(0xffffffffu, a1, off);
    }
    if (lane == 0) {
        g_s2[row] = a0;
        g_s2[row + 1] = a1;
        const int b0 = min(max((int)((a0 - RMIN) * BSCALE), 0), NB - 1);
        const int b1 = min(max((int)((a1 - RMIN) * BSCALE), 0), NB - 1);
        g_bidx[row] = b0;
        g_bidx[row + 1] = b1;
        atomicAdd(&g_cnt[b0], 1);
        atomicAdd(&g_cnt[b1], 1);
    }
}

// ---------------- 2. GEMM h1 = x @ W^T (+ fused s1) ----------------
__global__ void __launch_bounds__(256) kgemm(const float* __restrict__ X,
                                             const float* __restrict__ W,
                                             const float* __restrict__ w1) {
    __shared__ float xs[2][32 * 64];
    __shared__ float ws[2][32 * 64];
    const int t = threadIdx.x;
    const int row0 = blockIdx.x * 64;

    const int rl = t >> 2;
    const int kq = (t & 3) * 8;
    const int cs = rl ^ ((t & 3) << 3);
    const float* xp = X + (size_t)(row0 + rl) * KD + kq;
    const float* wp = W + (size_t)rl * KD + kq;

    float4 xa, xb, wa, wb;
    xa = *(const float4*)(xp + 0);  xb = *(const float4*)(xp + 4);
    wa = *(const float4*)(wp + 0);  wb = *(const float4*)(wp + 4);
    {
        float xv[8] = {xa.x, xa.y, xa.z, xa.w, xb.x, xb.y, xb.z, xb.w};
        float wv[8] = {wa.x, wa.y, wa.z, wa.w, wb.x, wb.y, wb.z, wb.w};
#pragma unroll
        for (int i = 0; i < 8; ++i) {
            xs[0][(kq + i) * 64 + cs] = xv[i];
            ws[0][(kq + i) * 64 + cs] = wv[i];
        }
    }
    __syncthreads();

    const int tr = t >> 4, tc = t & 15;
    const int r0 = tr * 4, c0 = tc * 4;
    float acc[4][4];
#pragma unroll
    for (int a = 0; a < 4; ++a)
#pragma unroll
        for (int b = 0; b < 4; ++b) acc[a][b] = 0.f;

    for (int ch = 0; ch < 16; ++ch) {
        const int cur = ch & 1;
        if (ch < 15) {
            const int ko = (ch + 1) * 32;
            xa = *(const float4*)(xp + ko);     xb = *(const float4*)(xp + ko + 4);
            wa = *(const float4*)(wp + ko);     wb = *(const float4*)(wp + ko + 4);
        }
#pragma unroll
        for (int kk = 0; kk < 32; ++kk) {
            const int swk = ((kk >> 3) & 3) << 3;
            float4 xv = *(const float4*)&xs[cur][kk * 64 + (r0 ^ swk)];
            float4 wv = *(const float4*)&ws[cur][kk * 64 + (c0 ^ swk)];
            acc[0][0] += xv.x * wv.x; acc[0][1] += xv.x * wv.y; acc[0][2] += xv.x * wv.z; acc[0][3] += xv.x * wv.w;
            acc[1][0] += xv.y * wv.x; acc[1][1] += xv.y * wv.y; acc[1][2] += xv.y * wv.z; acc[1][3] += xv.y * wv.w;
            acc[2][0] += xv.z * wv.x; acc[2][1] += xv.z * wv.y; acc[2][2] += xv.z * wv.z; acc[2][3] += xv.z * wv.w;
            acc[3][0] += xv.w * wv.x; acc[3][1] += xv.w * wv.y; acc[3][2] += xv.w * wv.z; acc[3][3] += xv.w * wv.w;
        }
        if (ch < 15) {
            const int nb = (ch + 1) & 1;
            float xv[8] = {xa.x, xa.y, xa.z, xa.w, xb.x, xb.y, xb.z, xb.w};
            float wv[8] = {wa.x, wa.y, wa.z, wa.w, wb.x, wb.y, wb.z, wb.w};
#pragma unroll
            for (int i = 0; i < 8; ++i) {
                xs[nb][(kq + i) * 64 + cs] = xv[i];
                ws[nb][(kq + i) * 64 + cs] = wv[i];
            }
            __syncthreads();
        }
    }

    float w1v[4];
#pragma unroll
    for (int ci = 0; ci < 4; ++ci) w1v[ci] = w1[c0 + ci];
#pragma unroll
    for (int ri = 0; ri < 4; ++ri) {
        const int row = row0 + r0 + ri;
        *(float4*)&g_h1[(size_t)row * FF + c0] =
            make_float4(acc[ri][0], acc[ri][1], acc[ri][2], acc[ri][3]);
        float p = acc[ri][0] * w1v[0] + acc[ri][1] * w1v[1] +
                  acc[ri][2] * w1v[2] + acc[ri][3] * w1v[3];
        p += __shfl_down_sync(0xffffffffu, p, 8, 16);
        p += __shfl_down_sync(0xffffffffu, p, 4, 16);
        p += __shfl_down_sync(0xffffffffu, p, 2, 16);
        p += __shfl_down_sync(0xffffffffu, p, 1, 16);
        if (tc == 0) g_s1[row] = p;
    }
}

// ---------------- 3. kscat: block-0 scan (others overlap-spin) -> scatter -> clear cnt ----
__global__ void __launch_bounds__(256) kscat() {
    __shared__ int wsum[8];
    const int t = threadIdx.x;
    const int bid = blockIdx.x;
    const int w = t >> 5, lane = t & 31;

    if (bid == 0) {
        int v[32];
#pragma unroll
        for (int q = 0; q < 8; ++q) {
            int4 c4 = ((const int4*)g_cnt)[t * 8 + q];
            v[q * 4 + 0] = c4.x; v[q * 4 + 1] = c4.y;
            v[q * 4 + 2] = c4.z; v[q * 4 + 3] = c4.w;
        }
        int tot = 0;
#pragma unroll
        for (int i = 0; i < 32; ++i) tot += v[i];
        int inc = tot;
#pragma unroll
        for (int off = 1; off < 32; off <<= 1) {
            int u = __shfl_up_sync(0xffffffffu, inc, off);
            if (lane >= off) inc += u;
        }
        if (lane == 31) wsum[w] = inc;
        __syncthreads();
        if (w == 0 && lane < 8) {
            int u = wsum[lane];
#pragma unroll
            for (int off = 1; off < 8; off <<= 1) {
                int x = __shfl_up_sync(0x000000ffu, u, off);
                if (lane >= off) u += x;
            }
            wsum[lane] = u;
        }
        __syncthreads();
        int run = inc - tot + (w > 0 ? wsum[w - 1] : 0);
#pragma unroll
        for (int q = 0; q < 8; ++q) {
            int4 s4;
            s4.x = run; run += v[q * 4 + 0];
            s4.y = run; run += v[q * 4 + 1];
            s4.z = run; run += v[q * 4 + 2];
            s4.w = run; run += v[q * 4 + 3];
            ((int4*)g_start)[t * 8 + q] = s4;
            ((int4*)g_cursor)[t * 8 + q] = s4;
        }
        if (t == 0) g_start[NB] = NN;
        __threadfence();
        __syncthreads();
        if (t == 0) atomicExch(&g_scanflag, 1u);
    } else {
        if (t == 0) {
            while (((volatile unsigned int*)&g_scanflag)[0] == 0u) __nanosleep(64);
        }
        __syncthreads();
        __threadfence();
    }

    {
        const int j = bid * 256 + t;
        const int b = g_bidx[j];
        const int pos = atomicAdd(&g_cursor[b], 1);
        g_sidx[pos] = j;
        g_skey[pos] = g_s2[j];
    }
    g_cnt[bid * 256 + t] = 0;
}

// ---------------- 4. kbsort: warp bitonic per bucket (deterministic) ----------------
__global__ void __launch_bounds__(256) kbsort() {
    const int wrp = threadIdx.x >> 5, lane = threadIdx.x & 31;
    const int b = blockIdx.x * 8 + wrp;
    const int s = g_start[b];
    const int m = g_start[b + 1] - s;
    if (m <= 1) return;
    if (m <= 32) {
        float key; int idx;
        if (lane < m) { key = g_skey[s + lane]; idx = g_sidx[s + lane]; }
        else { key = __int_as_float(0x7f800000); idx = 0x7f000000 + lane; }
#pragma unroll
        for (int k = 2; k <= 32; k <<= 1) {
#pragma unroll
            for (int j = k >> 1; j >= 1; j >>= 1) {
                float ok = __shfl_xor_sync(0xffffffffu, key, j);
                int   oi = __shfl_xor_sync(0xffffffffu, idx, j);
                const bool up = ((lane & k) == 0);
                const bool lower = ((lane & j) == 0);
                const bool oless = (ok < key) || (ok == key && oi < idx);
                const bool take = (lower == up) ? oless : !oless;
                if (take) { key = ok; idx = oi; }
            }
        }
        if (lane < m) { g_skey[s + lane] = key; g_sidx[s + lane] = idx; }
    } else if (lane == 0) {
        for (int a = s + 1; a < s + m; ++a) {
            const float k = g_skey[a];
            const int id = g_sidx[a];
            int p = a - 1;
            while (p >= s) {
                const float kp = g_skey[p];
                const int ip = g_sidx[p];
                if (kp > k || (kp == k && ip > id)) {
                    g_skey[p + 1] = kp; g_sidx[p + 1] = ip; --p;
                } else break;
            }
            g_skey[p + 1] = k; g_sidx[p + 1] = id;
        }
    }
}

// ---------------- 5. kphase1: FUSED pos+neg chunk scans + last-block offsets ----------------
// SA = pos table (row-reversed so prefix scan = suffix sums); SB = neg table.
// One fill (h1 loaded once), one scan phase (4 indep shfl chains/col), one writeback.
__global__ void __launch_bounds__(1024) kphase1() {
    __shared__ float SH[2 * CHUNK * 66];
    __shared__ float GT[8 * 66];
    __shared__ float kky[CHUNK];
    __shared__ int   jj[CHUNK];
    __shared__ unsigned int rank_s;
    float* const SA = SH;                    // pos, reversed
    float* const SB = SH + CHUNK * 66;       // neg
    const int tid = threadIdx.x;
    const int g = blockIdx.x;
    const int base = g * CHUNK;
    const int w = tid >> 5, lane = tid & 31;

    if (tid < CHUNK) {
        kky[tid] = g_skey[base + tid];
        jj[tid] = g_sidx[base + tid];
    }
    __syncthreads();

    // fill both tables from one h1 load
#pragma unroll
    for (int th = 0; th < 2; ++th) {
        const int t = w + th * 32;
        const int j = jj[t];
        const float key = kky[t];
        const float wp = __expf(key);
        const float wn = __expf(LRALPHA * key);
        const float h0 = g_h1[(size_t)j * FF + lane];
        const float hv = g_h1[(size_t)j * FF + 32 + lane];
        const int rrev = CHUNK - 1 - t;
        SA[rrev * 66 + lane] = wp * h0;
        SA[rrev * 66 + 32 + lane] = wp * hv;
        SB[t * 66 + lane] = wn * h0;
        SB[t * 66 + 32 + lane] = wn * hv;
        if (lane == 0) {
            SA[rrev * 66 + 64] = wp; SA[rrev * 66 + 65] = 0.f;
            SB[t * 66 + 64] = wn;    SB[t * 66 + 65] = 0.f;
        }
    }
    __syncthreads();

    // per-column inclusive scans (both tables at once): warp w handles cols w, w+32 (+64,65)
    for (int c = w; c < 66; c += 32) {
        float a0 = SA[lane * 66 + c];
        float a1 = SA[(lane + 32) * 66 + c];
        float b0 = SB[lane * 66 + c];
        float b1 = SB[(lane + 32) * 66 + c];
#pragma unroll
        for (int off = 1; off < 32; off <<= 1) {
            float ua0 = __shfl_up_sync(0xffffffffu, a0, off);
            float ua1 = __shfl_up_sync(0xffffffffu, a1, off);
            float ub0 = __shfl_up_sync(0xffffffffu, b0, off);
            float ub1 = __shfl_up_sync(0xffffffffu, b1, off);
            if (lane >= off) { a0 += ua0; a1 += ua1; b0 += ub0; b1 += ub1; }
        }
        a1 += __shfl_sync(0xffffffffu, a0, 31);
        b1 += __shfl_sync(0xffffffffu, b0, 31);
        SA[lane * 66 + c] = a0;
        SA[(lane + 32) * 66 + c] = a1;
        SB[lane * 66 + c] = b0;
        SB[(lane + 32) * 66 + c] = b1;
    }
    __syncthreads();

    // writeback both halves of Q + chunk totals
    for (int e = tid; e < CHUNK * 66; e += 1024) {
        const int t = e / 66, c = e - t * 66;
        g_Q[(size_t)(base + t) * QSTRIDE + c] = SA[(CHUNK - 1 - t) * 66 + c];
        g_Q[(size_t)(base + t) * QSTRIDE + 66 + c] = (t > 0) ? SB[(t - 1) * 66 + c] : 0.f;
    }
    if (tid < 65) {
        g_totPos[g * 66 + tid] = SA[(CHUNK - 1) * 66 + tid];
        g_totNeg[g * 66 + tid] = SB[(CHUNK - 1) * 66 + tid];
    }
    __syncthreads();

    if (tid == 0) { __threadfence(); rank_s = atomicAdd(&g_done, 1u); }
    __syncthreads();
    if (rank_s != NCHUNK - 1) return;
    __threadfence();

    const int grp = tid / 66, c = tid % 66;

    for (int e = tid; e < NCHUNK * 66; e += 1024) SH[e] = g_totPos[e];
    __syncthreads();
    if (tid < 528) {
        float acc = 0.f;
        for (int i = 15; i >= 0; --i) {
            const int gg = grp * 16 + i;
            const float v = SH[gg * 66 + c];
            SH[gg * 66 + c] = acc;
            acc += v;
        }
        GT[grp * 66 + c] = acc;
    }
    __syncthreads();
    if (tid < 66) {
        float acc = 0.f;
        for (int gg = 7; gg >= 0; --gg) {
            const float v = GT[gg * 66 + tid];
            GT[gg * 66 + tid] = acc;
            acc += v;
        }
        g_offPos[NCHUNK * 66 + tid] = 0.f;
    }
    __syncthreads();
    if (tid < 528) {
        const float o = GT[grp * 66 + c];
        for (int i = 0; i < 16; ++i) {
            const int gg = grp * 16 + i;
            g_offPos[gg * 66 + c] = SH[gg * 66 + c] + o;
        }
    }
    __syncthreads();

    for (int e = tid; e < NCHUNK * 66; e += 1024) SH[e] = g_totNeg[e];
    __syncthreads();
    if (tid < 528) {
        float acc = 0.f;
        for (int i = 0; i < 16; ++i) {
            const int gg = grp * 16 + i;
            const float v = SH[gg * 66 + c];
            SH[gg * 66 + c] = acc;
            acc += v;
        }
        GT[grp * 66 + c] = acc;
    }
    __syncthreads();
    if (tid < 66) {
        float acc = 0.f;
        for (int gg = 0; gg < 8; ++gg) {
            const float v = GT[gg * 66 + tid];
            GT[gg * 66 + tid] = acc;
            acc += v;
        }
        g_offNeg[NCHUNK * 66 + tid] = acc;
    }
    __syncthreads();
    if (tid < 528) {
        const float o = GT[grp * 66 + c];
        for (int i = 0; i < 16; ++i) {
            const int gg = grp * 16 + i;
            g_offNeg[gg * 66 + c] = SH[gg * 66 + c] + o;
        }
    }
}

// ---------------- 6. kquery: bucket-narrowed binary search + combine ----------------
__global__ void kquery(float* __restrict__ out) {
    const int t = threadIdx.x;
    const int w = t >> 5, lane = t & 31;
    const int i = blockIdx.x * 8 + w;

    const float s1v = g_s1[i];
    const float tau = -s1v;
    const float e1 = __expf(s1v);
    const float e1a = __expf(LRALPHA * s1v);

    const int bt = min(max((int)((tau - RMIN) * BSCALE), 0), NB - 1);
    int lo = g_start[bt], hi = g_start[bt + 1];
    while (lo < hi) {
        const int mid = (lo + hi) >> 1;
        if (g_skey[mid] < tau) lo = mid + 1; else hi = mid;
    }
    const int r = lo;

    float qA0 = 0.f, qA1 = 0.f, qAs = 0.f, qB0 = 0.f, qB1 = 0.f, qBs = 0.f;
    if (r < NN) {
        const float* q = g_Q + (size_t)r * QSTRIDE;
        qA0 = q[lane];       qA1 = q[lane + 32];       qAs = q[64];
        qB0 = q[66 + lane];  qB1 = q[66 + lane + 32];  qBs = q[66 + 64];
    }
    const int g = r >> 6;
    const float* op = g_offPos + g * 66;
    const float* on = g_offNeg + g * 66;
    const float A0 = qA0 + op[lane], A1 = qA1 + op[lane + 32], As = qAs + op[64];
    const float B0 = qB0 + on[lane], B1 = qB1 + on[lane + 32], Bs = qBs + on[64];

    const float den = e1 * As + e1a * Bs;
    const float inv = 1.0f / den;
    out[(size_t)i * FF + lane]      = (e1 * A0 + e1a * B0) * inv;
    out[(size_t)i * FF + 32 + lane] = (e1 * A1 + e1a * B1) * inv;
}

// ---------------- launch ----------------
extern "C" void kernel_launch(void* const* d_in, const int* in_sizes, int n_in,
                              void* d_out, int out_size) {
    const float* x  = (const float*)d_in[0];
    const float* nm = (const float*)d_in[1];
    const float* W  = (const float*)d_in[2];
    const float* w1 = (const float*)d_in[3];
    const float* w2 = (const float*)d_in[4];
    float* out = (float*)d_out;

    kprep<<<NN / 16, 256>>>(W, w2, nm);
    kgemm<<<NN / 64, 256>>>(x, W, w1);
    kscat<<<32, 256>>>();
    kbsort<<<NB / 8, 256>>>();
    kphase1<<<NCHUNK, 1024>>>();
    kquery<<<NN / 8, 256>>>(out);
}